// round 5
// baseline (speedup 1.0000x reference)
#include <cuda_runtime.h>
#include <math.h>
#include <stddef.h>

// Problem constants
#define BB    64
#define TT    1024
#define VOCAB 55
#define EMBED 64
#define HID   128

// Scratch (device globals: no allocations allowed)
__device__ float g_outs[BB * TT * HID];   // RNN layer-1 outputs (K and V of attention)
__device__ float g_q   [BB * TT * HID];   // Q = outs @ attn_w^T + attn_b
__device__ float g_ctx [BB * TT * HID];   // attention context
__device__ float g_tab0[VOCAB * HID];     // emb[v] @ w_ih0^T + b_ih0 + b_hh0

// ---------------------------------------------------------------------------
// Kernel A: precompute layer-0 input table per vocab entry
// ---------------------------------------------------------------------------
__global__ void tab0_kernel(const float* __restrict__ emb,
                            const float* __restrict__ w_ih0,
                            const float* __restrict__ b_ih0,
                            const float* __restrict__ b_hh0) {
    __shared__ float es[EMBED];
    int v = blockIdx.x;
    int i = threadIdx.x;  // 128 threads
    if (i < EMBED) es[i] = emb[v * EMBED + i];
    __syncthreads();
    float acc = b_ih0[i] + b_hh0[i];
    #pragma unroll
    for (int e = 0; e < EMBED; e++)
        acc += es[e] * w_ih0[i * EMBED + e];
    g_tab0[v * HID + i] = acc;
}

// ---------------------------------------------------------------------------
// Kernel B: sequential 2-layer tanh RNN scan. One block per batch element.
// 512 threads; recurrent weights live in registers (96 floats/thread).
// warp w (0..15), lane l: output i = 8w + l/4, quad q = l&3 sums a j-slice.
// ---------------------------------------------------------------------------
__global__ __launch_bounds__(512, 1)
void rnn_kernel(const int*   __restrict__ x,
                const float* __restrict__ w_hh0,
                const float* __restrict__ w_ih1,
                const float* __restrict__ b_ih1,
                const float* __restrict__ w_hh1,
                const float* __restrict__ b_hh1) {
    __shared__ float tab0s[VOCAB * HID];
    __shared__ int   xs[TT];
    __shared__ __align__(16) float h0b[2][HID];
    __shared__ __align__(16) float h1b[2][HID];

    const int b = blockIdx.x;
    const int t = threadIdx.x;
    const int w = t >> 5;
    const int l = t & 31;
    const int i = w * 8 + (l >> 2);
    const int q = l & 3;

    for (int idx = t; idx < VOCAB * HID; idx += 512) tab0s[idx] = g_tab0[idx];
    for (int idx = t; idx < TT;          idx += 512) xs[idx]    = x[b * TT + idx];
    if (t < HID) { h0b[0][t] = 0.f; h0b[1][t] = 0.f; h1b[0][t] = 0.f; h1b[1][t] = 0.f; }

    // Register-resident weights
    float w0r[32];
    #pragma unroll
    for (int k = 0; k < 32; k++) w0r[k] = w_hh0[i * HID + q * 32 + k];
    float w1r[64];
    #pragma unroll
    for (int k = 0; k < 64; k++) {
        int jj = q * 64 + k;
        w1r[k] = (jj < HID) ? w_ih1[i * HID + jj] : w_hh1[i * HID + (jj - HID)];
    }
    const float c1 = b_ih1[i] + b_hh1[i];

    __syncthreads();

    float* outp = g_outs + (size_t)b * TT * HID;

    #pragma unroll 1
    for (int st = 0; st < TT; st++) {
        const int cur = st & 1, nxt = cur ^ 1;

        // ---- layer 0: h0_new = tanh(tab0[x_t] + h0 @ w_hh0^T) ----
        const float* h0p = &h0b[cur][q * 32];
        float a0 = 0.f, a1 = 0.f;
        #pragma unroll
        for (int k = 0; k < 32; k += 4) {
            float4 h4 = *(const float4*)(h0p + k);
            a0 = fmaf(h4.x, w0r[k],     a0);
            a1 = fmaf(h4.y, w0r[k + 1], a1);
            a0 = fmaf(h4.z, w0r[k + 2], a0);
            a1 = fmaf(h4.w, w0r[k + 3], a1);
        }
        float acc = a0 + a1;
        acc += __shfl_xor_sync(0xffffffffu, acc, 1);
        acc += __shfl_xor_sync(0xffffffffu, acc, 2);
        float h0n = tanhf(acc + tab0s[xs[st] * HID + i]);
        if (q == 0) h0b[nxt][i] = h0n;
        __syncthreads();

        // ---- layer 1: h1_new = tanh(h0_new @ w_ih1^T + h1 @ w_hh1^T + c1) ----
        const float* src = (q < 2) ? &h0b[nxt][q * 64] : &h1b[cur][(q - 2) * 64];
        a0 = 0.f; a1 = 0.f;
        #pragma unroll
        for (int k = 0; k < 64; k += 4) {
            float4 h4 = *(const float4*)(src + k);
            a0 = fmaf(h4.x, w1r[k],     a0);
            a1 = fmaf(h4.y, w1r[k + 1], a1);
            a0 = fmaf(h4.z, w1r[k + 2], a0);
            a1 = fmaf(h4.w, w1r[k + 3], a1);
        }
        acc = a0 + a1;
        acc += __shfl_xor_sync(0xffffffffu, acc, 1);
        acc += __shfl_xor_sync(0xffffffffu, acc, 2);
        float h1n = tanhf(acc + c1);
        if (q == 0) {
            h1b[nxt][i] = h1n;
            outp[st * HID + i] = h1n;
        }
        __syncthreads();
    }
}

// ---------------------------------------------------------------------------
// Kernel C: Q = outs @ attn_w^T + attn_b   (64-row tiles, 4x8 microtiles)
// dyn smem: wt[128][132] (attn_w transposed), ost[128][68] (outs transposed)
// ---------------------------------------------------------------------------
__global__ __launch_bounds__(256, 1)
void q_kernel(const float* __restrict__ attn_w, const float* __restrict__ attn_b) {
    extern __shared__ float smq[];
    float* wt  = smq;                 // [k=128][i stride 132]
    float* ost = smq + 128 * 132;     // [k=128][r stride 68]
    __shared__ float bs[HID];

    const int t = threadIdx.x;
    const int rg = t >> 4, cg = t & 15;
    const size_t rowbase = (size_t)blockIdx.x * 64;

    for (int idx = t; idx < HID * HID; idx += 256) {
        int i = idx >> 7, k = idx & 127;
        wt[k * 132 + i] = attn_w[idx];
    }
    for (int idx = t; idx < 64 * HID; idx += 256) {
        int r = idx >> 7, k = idx & 127;
        ost[k * 68 + r] = g_outs[(rowbase + r) * HID + k];
    }
    if (t < HID) bs[t] = attn_b[t];
    __syncthreads();

    float acc[4][8];
    #pragma unroll
    for (int rr = 0; rr < 4; rr++)
        #pragma unroll
        for (int cc = 0; cc < 8; cc++) acc[rr][cc] = 0.f;

    #pragma unroll 4
    for (int k = 0; k < HID; k++) {
        float4 q4 = *(const float4*)(ost + k * 68 + rg * 4);
        float4 wa = *(const float4*)(wt + k * 132 + cg * 8);
        float4 wb = *(const float4*)(wt + k * 132 + cg * 8 + 4);
        float qv[4] = {q4.x, q4.y, q4.z, q4.w};
        float wv[8] = {wa.x, wa.y, wa.z, wa.w, wb.x, wb.y, wb.z, wb.w};
        #pragma unroll
        for (int rr = 0; rr < 4; rr++)
            #pragma unroll
            for (int cc = 0; cc < 8; cc++)
                acc[rr][cc] = fmaf(qv[rr], wv[cc], acc[rr][cc]);
    }

    #pragma unroll
    for (int rr = 0; rr < 4; rr++) {
        size_t row = rowbase + rg * 4 + rr;
        float4 o0 = make_float4(acc[rr][0] + bs[cg * 8 + 0], acc[rr][1] + bs[cg * 8 + 1],
                                acc[rr][2] + bs[cg * 8 + 2], acc[rr][3] + bs[cg * 8 + 3]);
        float4 o1 = make_float4(acc[rr][4] + bs[cg * 8 + 4], acc[rr][5] + bs[cg * 8 + 5],
                                acc[rr][6] + bs[cg * 8 + 6], acc[rr][7] + bs[cg * 8 + 7]);
        *(float4*)(g_q + row * HID + cg * 8)     = o0;
        *(float4*)(g_q + row * HID + cg * 8 + 4) = o1;
    }
}

// ---------------------------------------------------------------------------
// Kernel D: causal flash attention (fp32, online softmax).
// Block = (qt, b): 64 query rows, loops over qt/2+1 key tiles of 128.
// dyn smem: Qst[128][68], Kst[128][132], Ks[128][132], St[128][68] = 200 KB
// ---------------------------------------------------------------------------
__global__ __launch_bounds__(256, 1)
void attn_kernel() {
    extern __shared__ float sma[];
    float* Qst = sma;                               // [k][r], stride 68
    float* Kst = sma + 128 * 68;                    // [h][s], stride 132
    float* Ks  = sma + 128 * 68 + 128 * 132;        // [s][h], stride 132
    float* St  = sma + 128 * 68 + 2 * 128 * 132;    // [s][r], stride 68

    const int qt = blockIdx.x;
    const int b  = blockIdx.y;
    const int t  = threadIdx.x;
    const int rg = t >> 4, cg = t & 15;
    const int qrow0 = qt * 64;
    const float* Qg = g_q   + (size_t)b * TT * HID;
    const float* Og = g_outs + (size_t)b * TT * HID;

    for (int idx = t; idx < 64 * HID; idx += 256) {
        int r = idx >> 7, k = idx & 127;
        Qst[k * 68 + r] = Qg[(qrow0 + r) * HID + k] * 0.08838834764831845f; // 1/sqrt(128)
    }

    float m[4], lsum[4], O[4][8];
    #pragma unroll
    for (int rr = 0; rr < 4; rr++) {
        m[rr] = -1e30f; lsum[rr] = 0.f;
        #pragma unroll
        for (int cc = 0; cc < 8; cc++) O[rr][cc] = 0.f;
    }

    const int nkt = (qt >> 1) + 1;
    for (int kt = 0; kt < nkt; kt++) {
        __syncthreads();  // Qst ready (kt=0) / previous iter's Ks,St reads done
        for (int idx = t; idx < 128 * HID; idx += 256) {
            int s = idx >> 7, h = idx & 127;
            Ks[s * 132 + h] = Og[(kt * 128 + s) * HID + h];
        }
        __syncthreads();
        for (int idx = t; idx < 128 * HID; idx += 256) {
            int s = idx >> 7, h = idx & 127;
            Kst[h * 132 + s] = Ks[s * 132 + h];
        }
        __syncthreads();

        // S = Q K^T (scaled): thread microtile 4 rows x 8 key-cols
        float S[4][8];
        #pragma unroll
        for (int rr = 0; rr < 4; rr++)
            #pragma unroll
            for (int cc = 0; cc < 8; cc++) S[rr][cc] = 0.f;

        #pragma unroll 4
        for (int k = 0; k < HID; k++) {
            float4 q4 = *(const float4*)(Qst + k * 68 + rg * 4);
            float4 ka = *(const float4*)(Kst + k * 132 + cg * 8);
            float4 kb = *(const float4*)(Kst + k * 132 + cg * 8 + 4);
            float qv[4] = {q4.x, q4.y, q4.z, q4.w};
            float kv[8] = {ka.x, ka.y, ka.z, ka.w, kb.x, kb.y, kb.z, kb.w};
            #pragma unroll
            for (int rr = 0; rr < 4; rr++)
                #pragma unroll
                for (int cc = 0; cc < 8; cc++)
                    S[rr][cc] = fmaf(qv[rr], kv[cc], S[rr][cc]);
        }

        // Causal mask (only diagonal-overlapping tiles need it)
        if (kt * 128 + 127 > qrow0) {
            #pragma unroll
            for (int rr = 0; rr < 4; rr++) {
                int qi = qrow0 + rg * 4 + rr;
                #pragma unroll
                for (int cc = 0; cc < 8; cc++) {
                    int s = kt * 128 + cg * 8 + cc;
                    if (s > qi) S[rr][cc] = -1e30f;
                }
            }
        }

        // Online softmax update (row reductions across the 16-lane cg group)
        #pragma unroll
        for (int rr = 0; rr < 4; rr++) {
            float pm = S[rr][0];
            #pragma unroll
            for (int cc = 1; cc < 8; cc++) pm = fmaxf(pm, S[rr][cc]);
            pm = fmaxf(pm, __shfl_xor_sync(0xffffffffu, pm, 1));
            pm = fmaxf(pm, __shfl_xor_sync(0xffffffffu, pm, 2));
            pm = fmaxf(pm, __shfl_xor_sync(0xffffffffu, pm, 4));
            pm = fmaxf(pm, __shfl_xor_sync(0xffffffffu, pm, 8));
            float mn = fmaxf(m[rr], pm);
            float alpha = expf(m[rr] - mn);
            float rs = 0.f;
            #pragma unroll
            for (int cc = 0; cc < 8; cc++) {
                S[rr][cc] = expf(S[rr][cc] - mn);
                rs += S[rr][cc];
            }
            rs += __shfl_xor_sync(0xffffffffu, rs, 1);
            rs += __shfl_xor_sync(0xffffffffu, rs, 2);
            rs += __shfl_xor_sync(0xffffffffu, rs, 4);
            rs += __shfl_xor_sync(0xffffffffu, rs, 8);
            lsum[rr] = lsum[rr] * alpha + rs;
            m[rr] = mn;
            #pragma unroll
            for (int cc = 0; cc < 8; cc++) O[rr][cc] *= alpha;
        }

        // Store P transposed: St[s][r]
        #pragma unroll
        for (int rr = 0; rr < 4; rr++)
            #pragma unroll
            for (int cc = 0; cc < 8; cc++)
                St[(cg * 8 + cc) * 68 + rg * 4 + rr] = S[rr][cc];
        __syncthreads();

        // O += P @ V  (V = Ks in [s][h] layout)
        #pragma unroll 4
        for (int s = 0; s < 128; s++) {
            float4 p4 = *(const float4*)(St + s * 68 + rg * 4);
            float4 va = *(const float4*)(Ks + s * 132 + cg * 8);
            float4 vb = *(const float4*)(Ks + s * 132 + cg * 8 + 4);
            float pv[4] = {p4.x, p4.y, p4.z, p4.w};
            float vv[8] = {va.x, va.y, va.z, va.w, vb.x, vb.y, vb.z, vb.w};
            #pragma unroll
            for (int rr = 0; rr < 4; rr++)
                #pragma unroll
                for (int cc = 0; cc < 8; cc++)
                    O[rr][cc] = fmaf(pv[rr], vv[cc], O[rr][cc]);
        }
    }

    // Finalize & write context
    float* Cg = g_ctx + (size_t)b * TT * HID;
    #pragma unroll
    for (int rr = 0; rr < 4; rr++) {
        float inv = 1.0f / lsum[rr];
        size_t row = (size_t)qrow0 + rg * 4 + rr;
        float4 o0 = make_float4(O[rr][0] * inv, O[rr][1] * inv, O[rr][2] * inv, O[rr][3] * inv);
        float4 o1 = make_float4(O[rr][4] * inv, O[rr][5] * inv, O[rr][6] * inv, O[rr][7] * inv);
        *(float4*)(Cg + row * HID + cg * 8)     = o0;
        *(float4*)(Cg + row * HID + cg * 8 + 4) = o1;
    }
}

// ---------------------------------------------------------------------------
// Kernel E: logits = [outs, context] @ fc_w^T + fc_b   (16-row blocks)
// dyn smem: fwt[256][56] (fc_w transposed), xst[256][20] (combined transposed)
// ---------------------------------------------------------------------------
__global__ __launch_bounds__(256, 1)
void fc_kernel(const float* __restrict__ fc_w, const float* __restrict__ fc_b,
               float* __restrict__ out) {
    extern __shared__ float smf[];
    float* fwt = smf;                 // [k=256][c stride 56]
    float* xst = smf + 256 * 56;      // [k=256][r stride 20]

    const int t = threadIdx.x;
    const int c  = t & 63;
    const int rg = t >> 6;   // 0..3 -> rows rg*4..rg*4+3
    const size_t rowbase = (size_t)blockIdx.x * 16;

    for (int idx = t; idx < VOCAB * 256; idx += 256) {
        int cc = idx >> 8, k = idx & 255;
        fwt[k * 56 + cc] = fc_w[idx];
    }
    for (int idx = t; idx < 16 * 256; idx += 256) {
        int r = idx >> 8, k = idx & 255;
        size_t row = rowbase + r;
        float v = (k < HID) ? g_outs[row * HID + k] : g_ctx[row * HID + (k - HID)];
        xst[k * 20 + r] = v;
    }
    __syncthreads();

    if (c < VOCAB) {
        float a0 = 0.f, a1 = 0.f, a2 = 0.f, a3 = 0.f;
        #pragma unroll 4
        for (int k = 0; k < 256; k++) {
            float4 x4 = *(const float4*)(xst + k * 20 + rg * 4);
            float wv = fwt[k * 56 + c];
            a0 = fmaf(x4.x, wv, a0);
            a1 = fmaf(x4.y, wv, a1);
            a2 = fmaf(x4.z, wv, a2);
            a3 = fmaf(x4.w, wv, a3);
        }
        float bb = fc_b[c];
        out[(rowbase + rg * 4 + 0) * VOCAB + c] = a0 + bb;
        out[(rowbase + rg * 4 + 1) * VOCAB + c] = a1 + bb;
        out[(rowbase + rg * 4 + 2) * VOCAB + c] = a2 + bb;
        out[(rowbase + rg * 4 + 3) * VOCAB + c] = a3 + bb;
    }
}

// ---------------------------------------------------------------------------
extern "C" void kernel_launch(void* const* d_in, const int* in_sizes, int n_in,
                              void* d_out, int out_size) {
    const int*   x      = (const int*)  d_in[0];
    const float* emb    = (const float*)d_in[1];
    const float* w_ih0  = (const float*)d_in[2];
    const float* b_ih0  = (const float*)d_in[3];
    const float* w_hh0  = (const float*)d_in[4];
    const float* b_hh0  = (const float*)d_in[5];
    const float* w_ih1  = (const float*)d_in[6];
    const float* b_ih1  = (const float*)d_in[7];
    const float* w_hh1  = (const float*)d_in[8];
    const float* b_hh1  = (const float*)d_in[9];
    const float* attn_w = (const float*)d_in[10];
    const float* attn_b = (const float*)d_in[11];
    const float* fc_w   = (const float*)d_in[12];
    const float* fc_b   = (const float*)d_in[13];
    float* out = (float*)d_out;

    const int QSMEM = (128 * 132 + 128 * 68) * 4;                // 102400
    const int ASMEM = (128 * 68 + 2 * 128 * 132 + 128 * 68) * 4; // 204800
    const int FSMEM = (256 * 56 + 256 * 20) * 4;                 // 77824
    cudaFuncSetAttribute((const void*)q_kernel,
                         cudaFuncAttributeMaxDynamicSharedMemorySize, QSMEM);
    cudaFuncSetAttribute((const void*)attn_kernel,
                         cudaFuncAttributeMaxDynamicSharedMemorySize, ASMEM);
    cudaFuncSetAttribute((const void*)fc_kernel,
                         cudaFuncAttributeMaxDynamicSharedMemorySize, FSMEM);

    tab0_kernel<<<VOCAB, HID>>>(emb, w_ih0, b_ih0, b_hh0);
    rnn_kernel<<<BB, 512>>>(x, w_hh0, w_ih1, b_ih1, w_hh1, b_hh1);
    q_kernel<<<(BB * TT) / 64, 256, QSMEM>>>(attn_w, attn_b);
    attn_kernel<<<dim3(TT / 64, BB), 256, ASMEM>>>();
    fc_kernel<<<(BB * TT) / 16, 256, FSMEM>>>(fc_w, fc_b, out);
}

// round 6
// speedup vs baseline: 2.1231x; 2.1231x over previous
#include <cuda_runtime.h>
#include <math.h>
#include <stddef.h>

// Problem constants
#define BB    64
#define TT    1024
#define VOCAB 55
#define EMBED 64
#define HID   128

typedef unsigned long long u64;

// Scratch (device globals: no allocations allowed)
__device__ float g_outs[BB * TT * HID];   // RNN layer-1 outputs (K and V of attention)
__device__ float g_q   [BB * TT * HID];   // Q = outs @ attn_w^T + attn_b
__device__ float g_ctx [BB * TT * HID];   // attention context
__device__ float g_tab0[VOCAB * HID];     // emb[v] @ w_ih0^T + b_ih0 + b_hh0

// ---------------------------------------------------------------------------
// Packed f32x2 helpers (ptxas will not auto-fuse; inline PTX required)
// ---------------------------------------------------------------------------
__device__ __forceinline__ u64 fma2(u64 a, u64 b, u64 c) {
    u64 d; asm("fma.rn.f32x2 %0, %1, %2, %3;" : "=l"(d) : "l"(a), "l"(b), "l"(c));
    return d;
}
__device__ __forceinline__ u64 add2(u64 a, u64 b) {
    u64 d; asm("add.rn.f32x2 %0, %1, %2;" : "=l"(d) : "l"(a), "l"(b));
    return d;
}
__device__ __forceinline__ u64 mul2(u64 a, u64 b) {
    u64 d; asm("mul.rn.f32x2 %0, %1, %2;" : "=l"(d) : "l"(a), "l"(b));
    return d;
}
__device__ __forceinline__ u64 splat2(float v) {
    u64 r; asm("mov.b64 %0, {%1, %1};" : "=l"(r) : "f"(v));
    return r;
}
__device__ __forceinline__ float2 unpack2(u64 v) {
    float lo, hi; asm("mov.b64 {%0, %1}, %2;" : "=f"(lo), "=f"(hi) : "l"(v));
    return make_float2(lo, hi);
}
// tanh via exp: exact at |x| saturation, rel err ~1e-6
__device__ __forceinline__ float tanh_fast(float x) {
    float e = __expf(2.0f * x);
    return 1.0f - __fdividef(2.0f, e + 1.0f);
}

// ---------------------------------------------------------------------------
// Kernel A: precompute layer-0 input table per vocab entry
// ---------------------------------------------------------------------------
__global__ void tab0_kernel(const float* __restrict__ emb,
                            const float* __restrict__ w_ih0,
                            const float* __restrict__ b_ih0,
                            const float* __restrict__ b_hh0) {
    __shared__ float es[EMBED];
    int v = blockIdx.x;
    int i = threadIdx.x;  // 128 threads
    if (i < EMBED) es[i] = emb[v * EMBED + i];
    __syncthreads();
    float acc = b_ih0[i] + b_hh0[i];
    #pragma unroll
    for (int e = 0; e < EMBED; e++)
        acc += es[e] * w_ih0[i * EMBED + e];
    g_tab0[v * HID + i] = acc;
}

// ---------------------------------------------------------------------------
// Kernel B: sequential 2-layer tanh RNN. One block per batch element.
// 256 threads: i = t>>1 (output), q = t&1 (j-half). Weights packed f32x2 in
// registers: 32+64 u64 = 192 float-regs/thread (cap 256 at 256 thr -> no spill)
// ---------------------------------------------------------------------------
__global__ __launch_bounds__(256, 1)
void rnn_kernel(const int*   __restrict__ x,
                const float* __restrict__ w_hh0,
                const float* __restrict__ w_ih1,
                const float* __restrict__ b_ih1,
                const float* __restrict__ w_hh1,
                const float* __restrict__ b_hh1) {
    __shared__ float tab0s[VOCAB * HID];
    __shared__ int   xs[TT];
    __shared__ __align__(16) float h0b[2][HID];
    __shared__ __align__(16) float h1b[2][HID];

    const int b = blockIdx.x;
    const int t = threadIdx.x;
    const int i = t >> 1;
    const int q = t & 1;

    for (int idx = t; idx < VOCAB * HID; idx += 256) tab0s[idx] = g_tab0[idx];
    for (int idx = t; idx < TT;          idx += 256) xs[idx]    = x[b * TT + idx];
    if (t < HID) { h0b[0][t] = 0.f; h0b[1][t] = 0.f; h1b[0][t] = 0.f; h1b[1][t] = 0.f; }

    // Register-resident packed weights
    u64 w0r[32];  // w_hh0[i][q*64 .. q*64+63]
    {
        const ulonglong2* wp = (const ulonglong2*)(w_hh0 + i * HID + q * 64);
        #pragma unroll
        for (int m = 0; m < 16; m++) { ulonglong2 v = wp[m]; w0r[2*m] = v.x; w0r[2*m+1] = v.y; }
    }
    u64 w1r[64];  // q==0: w_ih1 row i; q==1: w_hh1 row i
    {
        const ulonglong2* wp = (const ulonglong2*)((q ? w_hh1 : w_ih1) + i * HID);
        #pragma unroll
        for (int m = 0; m < 32; m++) { ulonglong2 v = wp[m]; w1r[2*m] = v.x; w1r[2*m+1] = v.y; }
    }
    const float c1 = b_ih1[i] + b_hh1[i];

    __syncthreads();

    float* outp = g_outs + (size_t)b * TT * HID;

    #pragma unroll 1
    for (int st = 0; st < TT; st++) {
        const int cur = st & 1, nxt = cur ^ 1;
        const float tb = tab0s[xs[st] * HID + i];  // prefetch (independent)

        // ---- layer 0: h0_new = tanh(tab0[x_t] + h0 @ w_hh0^T) ----
        {
            const ulonglong2* hp = (const ulonglong2*)(&h0b[cur][q * 64]);
            u64 a0 = 0, a1 = 0, a2 = 0, a3 = 0;
            #pragma unroll
            for (int m = 0; m < 16; m += 2) {
                ulonglong2 ha = hp[m], hb = hp[m + 1];
                a0 = fma2(ha.x, w0r[2*m],     a0);
                a1 = fma2(ha.y, w0r[2*m + 1], a1);
                a2 = fma2(hb.x, w0r[2*m + 2], a2);
                a3 = fma2(hb.y, w0r[2*m + 3], a3);
            }
            float2 s = unpack2(add2(add2(a0, a1), add2(a2, a3)));
            float acc = s.x + s.y;
            acc += __shfl_xor_sync(0xffffffffu, acc, 1);
            float h0n = tanh_fast(acc + tb);
            if (!q) h0b[nxt][i] = h0n;
        }
        __syncthreads();

        // ---- layer 1: h1_new = tanh(h0_new @ w_ih1^T + h1 @ w_hh1^T + c1) ----
        {
            const ulonglong2* sp = (const ulonglong2*)(q ? &h1b[cur][0] : &h0b[nxt][0]);
            u64 a0 = 0, a1 = 0, a2 = 0, a3 = 0;
            #pragma unroll
            for (int m = 0; m < 32; m += 2) {
                ulonglong2 ha = sp[m], hb = sp[m + 1];
                a0 = fma2(ha.x, w1r[2*m],     a0);
                a1 = fma2(ha.y, w1r[2*m + 1], a1);
                a2 = fma2(hb.x, w1r[2*m + 2], a2);
                a3 = fma2(hb.y, w1r[2*m + 3], a3);
            }
            float2 s = unpack2(add2(add2(a0, a1), add2(a2, a3)));
            float acc = s.x + s.y;
            acc += __shfl_xor_sync(0xffffffffu, acc, 1);
            float h1n = tanh_fast(acc + c1);
            if (!q) {
                h1b[nxt][i] = h1n;
                outp[st * HID + i] = h1n;
            }
        }
        __syncthreads();
    }
}

// ---------------------------------------------------------------------------
// Kernel C: Q = outs @ attn_w^T + attn_b   (64-row tiles, 4x8 microtiles)
// ---------------------------------------------------------------------------
__global__ __launch_bounds__(256, 1)
void q_kernel(const float* __restrict__ attn_w, const float* __restrict__ attn_b) {
    extern __shared__ float smq[];
    float* wt  = smq;                 // [k=128][i stride 132]
    float* ost = smq + 128 * 132;     // [k=128][r stride 68]
    __shared__ float bs[HID];

    const int t = threadIdx.x;
    const int rg = t >> 4, cg = t & 15;
    const size_t rowbase = (size_t)blockIdx.x * 64;

    for (int idx = t; idx < HID * HID; idx += 256) {
        int i = idx >> 7, k = idx & 127;
        wt[k * 132 + i] = attn_w[idx];
    }
    for (int idx = t; idx < 64 * HID; idx += 256) {
        int r = idx >> 7, k = idx & 127;
        ost[k * 68 + r] = g_outs[(rowbase + r) * HID + k];
    }
    if (t < HID) bs[t] = attn_b[t];
    __syncthreads();

    u64 acc[4][4];
    #pragma unroll
    for (int rr = 0; rr < 4; rr++)
        #pragma unroll
        for (int c = 0; c < 4; c++) acc[rr][c] = 0ull;

    #pragma unroll 2
    for (int k = 0; k < HID; k++) {
        float4 q4 = *(const float4*)(ost + k * 68 + rg * 4);
        ulonglong2 w0 = *(const ulonglong2*)(wt + k * 132 + cg * 8);
        ulonglong2 w1 = *(const ulonglong2*)(wt + k * 132 + cg * 8 + 4);
        float qv[4] = {q4.x, q4.y, q4.z, q4.w};
        #pragma unroll
        for (int rr = 0; rr < 4; rr++) {
            u64 qs = splat2(qv[rr]);
            acc[rr][0] = fma2(qs, w0.x, acc[rr][0]);
            acc[rr][1] = fma2(qs, w0.y, acc[rr][1]);
            acc[rr][2] = fma2(qs, w1.x, acc[rr][2]);
            acc[rr][3] = fma2(qs, w1.y, acc[rr][3]);
        }
    }

    #pragma unroll
    for (int rr = 0; rr < 4; rr++) {
        size_t row = rowbase + rg * 4 + rr;
        float o[8];
        #pragma unroll
        for (int c = 0; c < 4; c++) {
            float2 p = unpack2(acc[rr][c]);
            o[2*c] = p.x + bs[cg * 8 + 2*c];
            o[2*c+1] = p.y + bs[cg * 8 + 2*c + 1];
        }
        *(float4*)(g_q + row * HID + cg * 8)     = make_float4(o[0], o[1], o[2], o[3]);
        *(float4*)(g_q + row * HID + cg * 8 + 4) = make_float4(o[4], o[5], o[6], o[7]);
    }
}

// ---------------------------------------------------------------------------
// Kernel D: causal flash attention (fp32, online softmax, f32x2 packed FMA).
// Block = (qt, b): 64 query rows, loops over qt/2+1 key tiles of 128.
// dyn smem: Qst[128][68], Kst[128][132], Ks[128][132], St[128][68] = 200 KB
// ---------------------------------------------------------------------------
__global__ __launch_bounds__(256, 1)
void attn_kernel() {
    extern __shared__ float sma[];
    float* Qst = sma;                               // [k][r], stride 68
    float* Kst = sma + 128 * 68;                    // [h][s], stride 132
    float* Ks  = sma + 128 * 68 + 128 * 132;        // [s][h], stride 132
    float* St  = sma + 128 * 68 + 2 * 128 * 132;    // [s][r-chunk xor-swizzled], stride 68

    const int qt = blockIdx.x;
    const int b  = blockIdx.y;
    const int t  = threadIdx.x;
    const int rg = t >> 4, cg = t & 15;
    const int qrow0 = qt * 64;
    const float* Qg = g_q    + (size_t)b * TT * HID;
    const float* Og = g_outs + (size_t)b * TT * HID;

    for (int idx = t; idx < 64 * HID; idx += 256) {
        int r = idx >> 7, k = idx & 127;
        Qst[k * 68 + r] = Qg[(qrow0 + r) * HID + k] * 0.08838834764831845f; // 1/sqrt(128)
    }

    float m[4], lsum[4];
    u64 O2[4][4];
    #pragma unroll
    for (int rr = 0; rr < 4; rr++) {
        m[rr] = -1e30f; lsum[rr] = 0.f;
        #pragma unroll
        for (int c = 0; c < 4; c++) O2[rr][c] = 0ull;
    }

    const int nkt = (qt >> 1) + 1;
    for (int kt = 0; kt < nkt; kt++) {
        __syncthreads();  // Qst ready (kt=0) / prior Ks,St reads done
        // Fused load + transpose of K/V tile
        for (int idx = t; idx < 128 * HID; idx += 256) {
            int s = idx >> 7, h = idx & 127;
            float v = Og[(kt * 128 + s) * HID + h];
            Ks [s * 132 + h] = v;
            Kst[h * 132 + s] = v;
        }
        __syncthreads();

        // S = Q K^T: cols packed (pairs of s), rows scalar-splatted
        u64 S2[4][4];
        #pragma unroll
        for (int rr = 0; rr < 4; rr++)
            #pragma unroll
            for (int c = 0; c < 4; c++) S2[rr][c] = 0ull;

        #pragma unroll 2
        for (int k = 0; k < HID; k++) {
            float4 q4 = *(const float4*)(Qst + k * 68 + rg * 4);
            ulonglong2 k0 = *(const ulonglong2*)(Kst + k * 132 + cg * 8);
            ulonglong2 k1 = *(const ulonglong2*)(Kst + k * 132 + cg * 8 + 4);
            float qv[4] = {q4.x, q4.y, q4.z, q4.w};
            #pragma unroll
            for (int rr = 0; rr < 4; rr++) {
                u64 qs = splat2(qv[rr]);
                S2[rr][0] = fma2(qs, k0.x, S2[rr][0]);
                S2[rr][1] = fma2(qs, k0.y, S2[rr][1]);
                S2[rr][2] = fma2(qs, k1.x, S2[rr][2]);
                S2[rr][3] = fma2(qs, k1.y, S2[rr][3]);
            }
        }

        float S[4][8];
        #pragma unroll
        for (int rr = 0; rr < 4; rr++)
            #pragma unroll
            for (int c = 0; c < 4; c++) {
                float2 p = unpack2(S2[rr][c]);
                S[rr][2*c] = p.x; S[rr][2*c+1] = p.y;
            }

        // Causal mask (only diagonal-overlapping tiles)
        if (kt * 128 + 127 > qrow0) {
            #pragma unroll
            for (int rr = 0; rr < 4; rr++) {
                int qi = qrow0 + rg * 4 + rr;
                #pragma unroll
                for (int cc = 0; cc < 8; cc++) {
                    int s = kt * 128 + cg * 8 + cc;
                    if (s > qi) S[rr][cc] = -1e30f;
                }
            }
        }

        // Online softmax (reductions across the 16-lane cg group)
        #pragma unroll
        for (int rr = 0; rr < 4; rr++) {
            float pm = S[rr][0];
            #pragma unroll
            for (int cc = 1; cc < 8; cc++) pm = fmaxf(pm, S[rr][cc]);
            pm = fmaxf(pm, __shfl_xor_sync(0xffffffffu, pm, 1));
            pm = fmaxf(pm, __shfl_xor_sync(0xffffffffu, pm, 2));
            pm = fmaxf(pm, __shfl_xor_sync(0xffffffffu, pm, 4));
            pm = fmaxf(pm, __shfl_xor_sync(0xffffffffu, pm, 8));
            float mn = fmaxf(m[rr], pm);
            float alpha = __expf(m[rr] - mn);
            float rs = 0.f;
            #pragma unroll
            for (int cc = 0; cc < 8; cc++) {
                S[rr][cc] = __expf(S[rr][cc] - mn);
                rs += S[rr][cc];
            }
            rs += __shfl_xor_sync(0xffffffffu, rs, 1);
            rs += __shfl_xor_sync(0xffffffffu, rs, 2);
            rs += __shfl_xor_sync(0xffffffffu, rs, 4);
            rs += __shfl_xor_sync(0xffffffffu, rs, 8);
            lsum[rr] = lsum[rr] * alpha + rs;
            m[rr] = mn;
            u64 as = splat2(alpha);
            #pragma unroll
            for (int c = 0; c < 4; c++) O2[rr][c] = mul2(O2[rr][c], as);
        }

        // Store P transposed with XOR swizzle on the 4-row chunk index:
        // chunk' = rg ^ (s>>3); here s>>3 == cg for our own stores.
        {
            int chw = (rg ^ cg) * 4;
            #pragma unroll
            for (int cc = 0; cc < 8; cc++)
                #pragma unroll
                for (int rr = 0; rr < 4; rr++)
                    St[(cg * 8 + cc) * 68 + chw + rr] = S[rr][cc];
        }
        __syncthreads();

        // O += P @ V  (V = Ks[s][h]; cols packed, P rows splatted)
        #pragma unroll 2
        for (int s = 0; s < 128; s++) {
            float4 p4 = *(const float4*)(St + s * 68 + ((rg ^ (s >> 3)) * 4));
            ulonglong2 v0 = *(const ulonglong2*)(Ks + s * 132 + cg * 8);
            ulonglong2 v1 = *(const ulonglong2*)(Ks + s * 132 + cg * 8 + 4);
            float pv[4] = {p4.x, p4.y, p4.z, p4.w};
            #pragma unroll
            for (int rr = 0; rr < 4; rr++) {
                u64 ps = splat2(pv[rr]);
                O2[rr][0] = fma2(ps, v0.x, O2[rr][0]);
                O2[rr][1] = fma2(ps, v0.y, O2[rr][1]);
                O2[rr][2] = fma2(ps, v1.x, O2[rr][2]);
                O2[rr][3] = fma2(ps, v1.y, O2[rr][3]);
            }
        }
    }

    // Finalize & write context
    float* Cg = g_ctx + (size_t)b * TT * HID;
    #pragma unroll
    for (int rr = 0; rr < 4; rr++) {
        float inv = 1.0f / lsum[rr];
        size_t row = (size_t)qrow0 + rg * 4 + rr;
        float o[8];
        #pragma unroll
        for (int c = 0; c < 4; c++) {
            float2 p = unpack2(O2[rr][c]);
            o[2*c] = p.x * inv; o[2*c+1] = p.y * inv;
        }
        *(float4*)(Cg + row * HID + cg * 8)     = make_float4(o[0], o[1], o[2], o[3]);
        *(float4*)(Cg + row * HID + cg * 8 + 4) = make_float4(o[4], o[5], o[6], o[7]);
    }
}

// ---------------------------------------------------------------------------
// Kernel E: logits = [outs, context] @ fc_w^T + fc_b   (16-row blocks)
// ---------------------------------------------------------------------------
__global__ __launch_bounds__(256, 1)
void fc_kernel(const float* __restrict__ fc_w, const float* __restrict__ fc_b,
               float* __restrict__ out) {
    extern __shared__ float smf[];
    float* fwt = smf;                 // [k=256][c stride 56]
    float* xst = smf + 256 * 56;      // [k=256][r stride 20]

    const int t = threadIdx.x;
    const int c  = t & 63;
    const int rg = t >> 6;   // 0..3 -> rows rg*4..rg*4+3
    const size_t rowbase = (size_t)blockIdx.x * 16;

    for (int idx = t; idx < VOCAB * 256; idx += 256) {
        int cc = idx >> 8, k = idx & 255;
        fwt[k * 56 + cc] = fc_w[idx];
    }
    for (int idx = t; idx < 16 * 256; idx += 256) {
        int r = idx >> 8, k = idx & 255;
        size_t row = rowbase + r;
        float v = (k < HID) ? g_outs[row * HID + k] : g_ctx[row * HID + (k - HID)];
        xst[k * 20 + r] = v;
    }
    __syncthreads();

    if (c < VOCAB) {
        float a0 = 0.f, a1 = 0.f, a2 = 0.f, a3 = 0.f;
        #pragma unroll 4
        for (int k = 0; k < 256; k++) {
            float4 x4 = *(const float4*)(xst + k * 20 + rg * 4);
            float wv = fwt[k * 56 + c];
            a0 = fmaf(x4.x, wv, a0);
            a1 = fmaf(x4.y, wv, a1);
            a2 = fmaf(x4.z, wv, a2);
            a3 = fmaf(x4.w, wv, a3);
        }
        float bb = fc_b[c];
        out[(rowbase + rg * 4 + 0) * VOCAB + c] = a0 + bb;
        out[(rowbase + rg * 4 + 1) * VOCAB + c] = a1 + bb;
        out[(rowbase + rg * 4 + 2) * VOCAB + c] = a2 + bb;
        out[(rowbase + rg * 4 + 3) * VOCAB + c] = a3 + bb;
    }
}

// ---------------------------------------------------------------------------
extern "C" void kernel_launch(void* const* d_in, const int* in_sizes, int n_in,
                              void* d_out, int out_size) {
    const int*   x      = (const int*)  d_in[0];
    const float* emb    = (const float*)d_in[1];
    const float* w_ih0  = (const float*)d_in[2];
    const float* b_ih0  = (const float*)d_in[3];
    const float* w_hh0  = (const float*)d_in[4];
    const float* b_hh0  = (const float*)d_in[5];
    const float* w_ih1  = (const float*)d_in[6];
    const float* b_ih1  = (const float*)d_in[7];
    const float* w_hh1  = (const float*)d_in[8];
    const float* b_hh1  = (const float*)d_in[9];
    const float* attn_w = (const float*)d_in[10];
    const float* attn_b = (const float*)d_in[11];
    const float* fc_w   = (const float*)d_in[12];
    const float* fc_b   = (const float*)d_in[13];
    float* out = (float*)d_out;

    const int QSMEM = (128 * 132 + 128 * 68) * 4;                // 102400
    const int ASMEM = (128 * 68 + 2 * 128 * 132 + 128 * 68) * 4; // 204800
    const int FSMEM = (256 * 56 + 256 * 20) * 4;                 // 77824
    cudaFuncSetAttribute((const void*)q_kernel,
                         cudaFuncAttributeMaxDynamicSharedMemorySize, QSMEM);
    cudaFuncSetAttribute((const void*)attn_kernel,
                         cudaFuncAttributeMaxDynamicSharedMemorySize, ASMEM);
    cudaFuncSetAttribute((const void*)fc_kernel,
                         cudaFuncAttributeMaxDynamicSharedMemorySize, FSMEM);

    tab0_kernel<<<VOCAB, HID>>>(emb, w_ih0, b_ih0, b_hh0);
    rnn_kernel<<<BB, 256>>>(x, w_hh0, w_ih1, b_ih1, w_hh1, b_hh1);
    q_kernel<<<(BB * TT) / 64, 256, QSMEM>>>(attn_w, attn_b);
    attn_kernel<<<dim3(TT / 64, BB), 256, ASMEM>>>();
    fc_kernel<<<(BB * TT) / 16, 256, FSMEM>>>(fc_w, fc_b, out);
}